// round 14
// baseline (speedup 1.0000x reference)
#include <cuda_runtime.h>
#include <cuda_fp16.h>

#define N_NODES 100000
#define N_EDGES 3200000
#define N_QUADS (N_EDGES / 4)   // 4 edges per thread (best measured config)
#define NODE_BLOCKS 296          // exactly 2 waves on 148 SMs for k_node

// Device-side PDL sync: wait until all upstream-grid writes are visible.
__device__ __forceinline__ void grid_dep_sync() {
#if __CUDA_ARCH__ >= 900
    cudaGridDependencySynchronize();
#endif
}

// ---------------- scratch (device globals; no allocation allowed) ----------
// g_deg: zero-initialized at module load; k_prescale re-zeroes each entry
// after consuming it, so the zero invariant holds for every call (no memset).
__device__ float   g_deg[N_NODES];
__device__ float   g_dinv[N_NODES];
__device__ __half2 g_y[N_NODES];     // f16x2(dinv[n] * x[n])   layer-1 source msgs
__device__ float2  g_agg1[N_NODES];  // (A+I) @ y               f32 accumulation
__device__ __half2 g_zs[N_NODES];    // f16x2(dinv[n] * z[n])   layer-2 source msgs

// Vector f32x2 reduction to global (PTX 8.1+, sm_90+). Halves atomic op count.
__device__ __forceinline__ void red_add_v2(float2* addr, float a, float b) {
    asm volatile("red.global.add.v2.f32 [%0], {%1, %2};"
                 :: "l"(addr), "f"(a), "f"(b) : "memory");
}

// K2: degree accumulation at destinations. Indices are harness inputs
// (independent); g_deg was zeroed by previous invocation's prescale.
__global__ void k_degree(const int* __restrict__ dst) {
    int i = blockIdx.x * blockDim.x + threadIdx.x;
    if (i < N_QUADS) {
        int4 d = reinterpret_cast<const int4*>(dst)[i];
        atomicAdd(&g_deg[d.x], 1.0f);
        atomicAdd(&g_deg[d.y], 1.0f);
        atomicAdd(&g_deg[d.z], 1.0f);
        atomicAdd(&g_deg[d.w], 1.0f);
    }
}

// K3: dinv = rsqrt(deg+1); y = dinv*x f16x2; agg1 init with f32 self-loop.
// Prologue: load x (input) before depending on k_degree's atomics.
__global__ void k_prescale(const float* __restrict__ x) {
    int n = blockIdx.x * blockDim.x + threadIdx.x;
    float2 xv = make_float2(0.f, 0.f);
    if (n < N_NODES) xv = reinterpret_cast<const float2*>(x)[n];   // independent
    grid_dep_sync();                                               // wait: g_deg
    if (n < N_NODES) {
        float dg = g_deg[n];
        g_deg[n] = 0.0f;                      // restore zero invariant
        float di = rsqrtf(dg + 1.0f);         // +1 = self-loop
        g_dinv[n] = di;
        float2 y  = make_float2(di * xv.x, di * xv.y);
        g_y[n]    = __floats2half2_rn(y.x, y.y);
        g_agg1[n] = y;                        // self-loop in full precision
    }
}

// K4: layer-1 aggregation: agg1[d] += y[s].
// Prologue: stream edge indices (inputs) before depending on prescale.
__global__ void k_agg1(const int* __restrict__ src,
                       const int* __restrict__ dst) {
    int i = blockIdx.x * blockDim.x + threadIdx.x;
    int4 s = make_int4(0, 0, 0, 0), d = make_int4(0, 0, 0, 0);
    bool v = (i < N_QUADS);
    if (v) {
        s = reinterpret_cast<const int4*>(src)[i];                 // independent
        d = reinterpret_cast<const int4*>(dst)[i];
    }
    grid_dep_sync();                                               // wait: g_y/g_agg1
    if (v) {
        float2 y0 = __half22float2(g_y[s.x]);
        float2 y1 = __half22float2(g_y[s.y]);
        float2 y2 = __half22float2(g_y[s.z]);
        float2 y3 = __half22float2(g_y[s.w]);
        red_add_v2(&g_agg1[d.x], y0.x, y0.y);
        red_add_v2(&g_agg1[d.y], y1.x, y1.y);
        red_add_v2(&g_agg1[d.z], y2.x, y2.y);
        red_add_v2(&g_agg1[d.w], y3.x, y3.y);
    }
}

// K5: per-node fused dense chain, grid-stride over exactly 2 waves (296 blocks)
//     so every SM runs the weight prologue exactly twice, no ragged tail.
__global__ void k_node(const float* __restrict__ W1,
                       const float* __restrict__ b1,
                       const float* __restrict__ W2,
                       float2* __restrict__ out) {
    __shared__ float4 sWp[64];   // {W1[j][0], W1[j][1], W2[0][j], W2[1][j]}
    __shared__ float  sb1[64];
    int t = threadIdx.x;
    if (t < 64) {
        sWp[t] = make_float4(W1[2 * t], W1[2 * t + 1], W2[t], W2[64 + t]);
        sb1[t] = b1[t];
    }
    __syncthreads();
    grid_dep_sync();                                               // wait: g_agg1

    int stride = gridDim.x * blockDim.x;
    for (int n = blockIdx.x * blockDim.x + t; n < N_NODES; n += stride) {
        float  di = g_dinv[n];
        float2 ag = g_agg1[n];
        float  ax = di * ag.x, ay = di * ag.y;

        float zx = 0.0f, zy = 0.0f;
#pragma unroll
        for (int j = 0; j < 64; j++) {
            float4 w = sWp[j];
            float h = fmaf(w.x, ax, fmaf(w.y, ay, sb1[j]));
            h = fmaxf(h, 0.0f);
            zx = fmaf(w.z, h, zx);
            zy = fmaf(w.w, h, zy);
        }
        float zsx = di * zx, zsy = di * zy;
        g_zs[n] = __floats2half2_rn(zsx, zsy);
        out[n]  = make_float2(zsx, zsy);      // self-loop in full precision
    }
}

// K6: layer-2 aggregation directly into d_out: out[d] += zs[s].
__global__ void k_agg2(const int* __restrict__ src,
                       const int* __restrict__ dst,
                       float2* __restrict__ out) {
    int i = blockIdx.x * blockDim.x + threadIdx.x;
    int4 s = make_int4(0, 0, 0, 0), d = make_int4(0, 0, 0, 0);
    bool v = (i < N_QUADS);
    if (v) {
        s = reinterpret_cast<const int4*>(src)[i];                 // independent
        d = reinterpret_cast<const int4*>(dst)[i];
    }
    grid_dep_sync();                                               // wait: g_zs/out
    if (v) {
        float2 z0 = __half22float2(g_zs[s.x]);
        float2 z1 = __half22float2(g_zs[s.y]);
        float2 z2 = __half22float2(g_zs[s.z]);
        float2 z3 = __half22float2(g_zs[s.w]);
        red_add_v2(&out[d.x], z0.x, z0.y);
        red_add_v2(&out[d.y], z1.x, z1.y);
        red_add_v2(&out[d.z], z2.x, z2.y);
        red_add_v2(&out[d.w], z3.x, z3.y);
    }
}

// K7: destination post-scale + bias: out[n] = dinv[n]*out[n] + b2.
__global__ void k_final(const float* __restrict__ b2,
                        float2* __restrict__ out) {
    float bb0 = __ldg(&b2[0]), bb1 = __ldg(&b2[1]);                // independent
    grid_dep_sync();                                               // wait: out reds
    int n = blockIdx.x * blockDim.x + threadIdx.x;
    if (n < N_NODES) {
        float di = g_dinv[n];
        float2 o = out[n];
        out[n] = make_float2(fmaf(di, o.x, bb0), fmaf(di, o.y, bb1));
    }
}

// Host-side PDL launch wrapper (graph-capturable).
template <typename Kern, typename... Args>
static inline void pdl_launch(Kern k, int grid, int block, Args... args) {
    cudaLaunchConfig_t cfg = {};
    cfg.gridDim  = dim3(grid, 1, 1);
    cfg.blockDim = dim3(block, 1, 1);
    cfg.dynamicSmemBytes = 0;
    cfg.stream = 0;
    cudaLaunchAttribute attr[1];
    attr[0].id = cudaLaunchAttributeProgrammaticStreamSerialization;
    attr[0].val.programmaticStreamSerializationAllowed = 1;
    cfg.attrs = attr;
    cfg.numAttrs = 1;
    cudaLaunchKernelEx(&cfg, k, args...);
}

extern "C" void kernel_launch(void* const* d_in, const int* in_sizes, int n_in,
                              void* d_out, int out_size) {
    const float* x  = (const float*)d_in[0];
    const int*   ei = (const int*)d_in[1];
    const float* W1 = (const float*)d_in[2];
    const float* b1 = (const float*)d_in[3];
    const float* W2 = (const float*)d_in[4];
    const float* b2 = (const float*)d_in[5];
    float2*      out = (float2*)d_out;

    const int* src = ei;
    const int* dst = ei + N_EDGES;

    const int TB = 256;
    int nb_nodes = (N_NODES + TB - 1) / TB;
    int nb_quads = (N_QUADS + TB - 1) / TB;

    pdl_launch(k_degree,   nb_quads, TB, dst);
    pdl_launch(k_prescale, nb_nodes, TB, x);
    pdl_launch(k_agg1,     nb_quads, TB, src, dst);
    pdl_launch(k_node,     NODE_BLOCKS, TB, W1, b1, W2, out);
    pdl_launch(k_agg2,     nb_quads, TB, src, dst, out);
    pdl_launch(k_final,    nb_nodes, TB, b2, out);
}

// round 15
// speedup vs baseline: 1.0403x; 1.0403x over previous
#include <cuda_runtime.h>
#include <cuda_fp16.h>

#define N_NODES 100000
#define N_EDGES 3200000
#define N_QUADS (N_EDGES / 4)   // 4 edges per thread (best measured config)

// Device-side PDL sync: wait until all upstream-grid writes are visible.
__device__ __forceinline__ void grid_dep_sync() {
#if __CUDA_ARCH__ >= 900
    cudaGridDependencySynchronize();
#endif
}

// ---------------- scratch (device globals; no allocation allowed) ----------
// g_deg: zero-initialized at module load; k_prescale re-zeroes each entry
// after consuming it, so the zero invariant holds for every call (no memset).
__device__ float   g_deg[N_NODES];
__device__ float   g_dinv[N_NODES];
__device__ __half2 g_y[N_NODES];     // f16x2(dinv[n] * x[n])   layer-1 source msgs
__device__ float2  g_agg1[N_NODES];  // (A+I) @ y               f32 accumulation
__device__ __half2 g_zs[N_NODES];    // f16x2(dinv[n] * z[n])   layer-2 source msgs

// Vector f32x2 reduction to global (PTX 8.1+, sm_90+). Halves atomic op count.
__device__ __forceinline__ void red_add_v2(float2* addr, float a, float b) {
    asm volatile("red.global.add.v2.f32 [%0], {%1, %2};"
                 :: "l"(addr), "f"(a), "f"(b) : "memory");
}

// K2: degree accumulation at destinations. Indices are harness inputs
// (independent); g_deg was zeroed by previous invocation's prescale.
__global__ void k_degree(const int* __restrict__ dst) {
    int i = blockIdx.x * blockDim.x + threadIdx.x;
    if (i < N_QUADS) {
        int4 d = reinterpret_cast<const int4*>(dst)[i];
        atomicAdd(&g_deg[d.x], 1.0f);
        atomicAdd(&g_deg[d.y], 1.0f);
        atomicAdd(&g_deg[d.z], 1.0f);
        atomicAdd(&g_deg[d.w], 1.0f);
    }
}

// K3: dinv = rsqrt(deg+1); y = dinv*x f16x2; agg1 init with f32 self-loop.
// Prologue: load x (input) before depending on k_degree's atomics.
__global__ void k_prescale(const float* __restrict__ x) {
    int n = blockIdx.x * blockDim.x + threadIdx.x;
    float2 xv = make_float2(0.f, 0.f);
    if (n < N_NODES) xv = reinterpret_cast<const float2*>(x)[n];   // independent
    grid_dep_sync();                                               // wait: g_deg
    if (n < N_NODES) {
        float dg = g_deg[n];
        g_deg[n] = 0.0f;                      // restore zero invariant
        float di = rsqrtf(dg + 1.0f);         // +1 = self-loop
        g_dinv[n] = di;
        float2 y  = make_float2(di * xv.x, di * xv.y);
        g_y[n]    = __floats2half2_rn(y.x, y.y);
        g_agg1[n] = y;                        // self-loop in full precision
    }
}

// K4: layer-1 aggregation: agg1[d] += y[s].
// Prologue: stream edge indices (inputs) before depending on prescale.
__global__ void k_agg1(const int* __restrict__ src,
                       const int* __restrict__ dst) {
    int i = blockIdx.x * blockDim.x + threadIdx.x;
    int4 s = make_int4(0, 0, 0, 0), d = make_int4(0, 0, 0, 0);
    bool v = (i < N_QUADS);
    if (v) {
        s = reinterpret_cast<const int4*>(src)[i];                 // independent
        d = reinterpret_cast<const int4*>(dst)[i];
    }
    grid_dep_sync();                                               // wait: g_y/g_agg1
    if (v) {
        float2 y0 = __half22float2(g_y[s.x]);
        float2 y1 = __half22float2(g_y[s.y]);
        float2 y2 = __half22float2(g_y[s.z]);
        float2 y3 = __half22float2(g_y[s.w]);
        red_add_v2(&g_agg1[d.x], y0.x, y0.y);
        red_add_v2(&g_agg1[d.y], y1.x, y1.y);
        red_add_v2(&g_agg1[d.z], y2.x, y2.y);
        red_add_v2(&g_agg1[d.w], y3.x, y3.y);
    }
}

// K5: per-node fused dense chain, weights packed as float4 (R13 best config:
//     fixed grid, 1 thread/node, 34 regs).
__global__ void k_node(const float* __restrict__ W1,
                       const float* __restrict__ b1,
                       const float* __restrict__ W2,
                       float2* __restrict__ out) {
    __shared__ float4 sWp[64];   // {W1[j][0], W1[j][1], W2[0][j], W2[1][j]}
    __shared__ float  sb1[64];
    int t = threadIdx.x;
    if (t < 64) {
        sWp[t] = make_float4(W1[2 * t], W1[2 * t + 1], W2[t], W2[64 + t]);
        sb1[t] = b1[t];
    }
    __syncthreads();
    grid_dep_sync();                                               // wait: g_agg1

    int n = blockIdx.x * blockDim.x + t;
    if (n >= N_NODES) return;

    float  di = g_dinv[n];
    float2 ag = g_agg1[n];
    float  ax = di * ag.x, ay = di * ag.y;

    float zx = 0.0f, zy = 0.0f;
#pragma unroll
    for (int j = 0; j < 64; j++) {
        float4 w = sWp[j];
        float h = fmaf(w.x, ax, fmaf(w.y, ay, sb1[j]));
        h = fmaxf(h, 0.0f);
        zx = fmaf(w.z, h, zx);
        zy = fmaf(w.w, h, zy);
    }
    float zsx = di * zx, zsy = di * zy;
    g_zs[n] = __floats2half2_rn(zsx, zsy);
    out[n]  = make_float2(zsx, zsy);          // self-loop in full precision
}

// K6: layer-2 aggregation directly into d_out: out[d] += zs[s].
__global__ void k_agg2(const int* __restrict__ src,
                       const int* __restrict__ dst,
                       float2* __restrict__ out) {
    int i = blockIdx.x * blockDim.x + threadIdx.x;
    int4 s = make_int4(0, 0, 0, 0), d = make_int4(0, 0, 0, 0);
    bool v = (i < N_QUADS);
    if (v) {
        s = reinterpret_cast<const int4*>(src)[i];                 // independent
        d = reinterpret_cast<const int4*>(dst)[i];
    }
    grid_dep_sync();                                               // wait: g_zs/out
    if (v) {
        float2 z0 = __half22float2(g_zs[s.x]);
        float2 z1 = __half22float2(g_zs[s.y]);
        float2 z2 = __half22float2(g_zs[s.z]);
        float2 z3 = __half22float2(g_zs[s.w]);
        red_add_v2(&out[d.x], z0.x, z0.y);
        red_add_v2(&out[d.y], z1.x, z1.y);
        red_add_v2(&out[d.z], z2.x, z2.y);
        red_add_v2(&out[d.w], z3.x, z3.y);
    }
}

// K7: destination post-scale + bias: out[n] = dinv[n]*out[n] + b2.
__global__ void k_final(const float* __restrict__ b2,
                        float2* __restrict__ out) {
    float bb0 = __ldg(&b2[0]), bb1 = __ldg(&b2[1]);                // independent
    grid_dep_sync();                                               // wait: out reds
    int n = blockIdx.x * blockDim.x + threadIdx.x;
    if (n < N_NODES) {
        float di = g_dinv[n];
        float2 o = out[n];
        out[n] = make_float2(fmaf(di, o.x, bb0), fmaf(di, o.y, bb1));
    }
}

// Host-side PDL launch wrapper (graph-capturable).
template <typename Kern, typename... Args>
static inline void pdl_launch(Kern k, int grid, int block, Args... args) {
    cudaLaunchConfig_t cfg = {};
    cfg.gridDim  = dim3(grid, 1, 1);
    cfg.blockDim = dim3(block, 1, 1);
    cfg.dynamicSmemBytes = 0;
    cfg.stream = 0;
    cudaLaunchAttribute attr[1];
    attr[0].id = cudaLaunchAttributeProgrammaticStreamSerialization;
    attr[0].val.programmaticStreamSerializationAllowed = 1;
    cfg.attrs = attr;
    cfg.numAttrs = 1;
    cudaLaunchKernelEx(&cfg, k, args...);
}

extern "C" void kernel_launch(void* const* d_in, const int* in_sizes, int n_in,
                              void* d_out, int out_size) {
    const float* x  = (const float*)d_in[0];
    const int*   ei = (const int*)d_in[1];
    const float* W1 = (const float*)d_in[2];
    const float* b1 = (const float*)d_in[3];
    const float* W2 = (const float*)d_in[4];
    const float* b2 = (const float*)d_in[5];
    float2*      out = (float2*)d_out;

    const int* src = ei;
    const int* dst = ei + N_EDGES;

    const int TB = 256;
    int nb_nodes = (N_NODES + TB - 1) / TB;
    int nb_quads = (N_QUADS + TB - 1) / TB;

    pdl_launch(k_degree,   nb_quads, TB, dst);
    pdl_launch(k_prescale, nb_nodes, TB, x);
    pdl_launch(k_agg1,     nb_quads, TB, src, dst);
    pdl_launch(k_node,     nb_nodes, TB, W1, b1, W2, out);
    pdl_launch(k_agg2,     nb_quads, TB, src, dst, out);
    pdl_launch(k_final,    nb_nodes, TB, b2, out);
}

// round 16
// speedup vs baseline: 1.0433x; 1.0029x over previous
#include <cuda_runtime.h>
#include <cuda_fp16.h>

#define N_NODES 100000
#define N_EDGES 3200000
#define N_QUADS (N_EDGES / 4)   // 4 edges per thread (best measured config)

// Device-side PDL sync: wait until all upstream-grid writes are visible.
__device__ __forceinline__ void grid_dep_sync() {
#if __CUDA_ARCH__ >= 900
    cudaGridDependencySynchronize();
#endif
}

// ---------------- scratch (device globals; no allocation allowed) ----------
// g_deg: zero-initialized at module load; k_prescale re-zeroes each entry
// after consuming it, so the zero invariant holds for every call (no memset).
__device__ float   g_deg[N_NODES];
__device__ float   g_dinv[N_NODES];
__device__ __half2 g_y[N_NODES];     // f16x2(dinv[n] * x[n])   layer-1 source msgs
__device__ float2  g_agg1[N_NODES];  // (A+I) @ y               f32 accumulation
__device__ __half2 g_zs[N_NODES];    // f16x2(dinv[n] * z[n])   layer-2 source msgs

// Vector f32x2 reduction to global (PTX 8.1+, sm_90+). Halves atomic op count.
__device__ __forceinline__ void red_add_v2(float2* addr, float a, float b) {
    asm volatile("red.global.add.v2.f32 [%0], {%1, %2};"
                 :: "l"(addr), "f"(a), "f"(b) : "memory");
}

// K2: degree accumulation at destinations. Indices are harness inputs
// (independent); g_deg was zeroed by previous invocation's prescale.
__global__ void k_degree(const int* __restrict__ dst) {
    int i = blockIdx.x * blockDim.x + threadIdx.x;
    if (i < N_QUADS) {
        int4 d = reinterpret_cast<const int4*>(dst)[i];
        atomicAdd(&g_deg[d.x], 1.0f);
        atomicAdd(&g_deg[d.y], 1.0f);
        atomicAdd(&g_deg[d.z], 1.0f);
        atomicAdd(&g_deg[d.w], 1.0f);
    }
}

// K3: dinv = rsqrt(deg+1); y = dinv*x f16x2; agg1 init with f32 self-loop.
// Prologue: load x (input) before depending on k_degree's atomics.
__global__ void k_prescale(const float* __restrict__ x) {
    int n = blockIdx.x * blockDim.x + threadIdx.x;
    float2 xv = make_float2(0.f, 0.f);
    if (n < N_NODES) xv = reinterpret_cast<const float2*>(x)[n];   // independent
    grid_dep_sync();                                               // wait: g_deg
    if (n < N_NODES) {
        float dg = g_deg[n];
        g_deg[n] = 0.0f;                      // restore zero invariant
        float di = rsqrtf(dg + 1.0f);         // +1 = self-loop
        g_dinv[n] = di;
        float2 y  = make_float2(di * xv.x, di * xv.y);
        g_y[n]    = __floats2half2_rn(y.x, y.y);
        g_agg1[n] = y;                        // self-loop in full precision
    }
}

// K4: layer-1 aggregation: agg1[d] += y[s].
// Prologue: stream edge indices (inputs) before depending on prescale.
__global__ void k_agg1(const int* __restrict__ src,
                       const int* __restrict__ dst) {
    int i = blockIdx.x * blockDim.x + threadIdx.x;
    int4 s = make_int4(0, 0, 0, 0), d = make_int4(0, 0, 0, 0);
    bool v = (i < N_QUADS);
    if (v) {
        s = reinterpret_cast<const int4*>(src)[i];                 // independent
        d = reinterpret_cast<const int4*>(dst)[i];
    }
    grid_dep_sync();                                               // wait: g_y/g_agg1
    if (v) {
        float2 y0 = __half22float2(g_y[s.x]);
        float2 y1 = __half22float2(g_y[s.y]);
        float2 y2 = __half22float2(g_y[s.z]);
        float2 y3 = __half22float2(g_y[s.w]);
        red_add_v2(&g_agg1[d.x], y0.x, y0.y);
        red_add_v2(&g_agg1[d.y], y1.x, y1.y);
        red_add_v2(&g_agg1[d.z], y2.x, y2.y);
        red_add_v2(&g_agg1[d.w], y3.x, y3.y);
    }
}

// K5: per-node fused dense chain, weights packed as float4 (best config:
//     fixed grid, 1 thread/node, 34 regs).
__global__ void k_node(const float* __restrict__ W1,
                       const float* __restrict__ b1,
                       const float* __restrict__ W2,
                       float2* __restrict__ out) {
    __shared__ float4 sWp[64];   // {W1[j][0], W1[j][1], W2[0][j], W2[1][j]}
    __shared__ float  sb1[64];
    int t = threadIdx.x;
    if (t < 64) {
        sWp[t] = make_float4(W1[2 * t], W1[2 * t + 1], W2[t], W2[64 + t]);
        sb1[t] = b1[t];
    }
    __syncthreads();
    grid_dep_sync();                                               // wait: g_agg1

    int n = blockIdx.x * blockDim.x + t;
    if (n >= N_NODES) return;

    float  di = g_dinv[n];
    float2 ag = g_agg1[n];
    float  ax = di * ag.x, ay = di * ag.y;

    float zx = 0.0f, zy = 0.0f;
#pragma unroll
    for (int j = 0; j < 64; j++) {
        float4 w = sWp[j];
        float h = fmaf(w.x, ax, fmaf(w.y, ay, sb1[j]));
        h = fmaxf(h, 0.0f);
        zx = fmaf(w.z, h, zx);
        zy = fmaf(w.w, h, zy);
    }
    float zsx = di * zx, zsy = di * zy;
    g_zs[n] = __floats2half2_rn(zsx, zsy);
    out[n]  = make_float2(zsx, zsy);          // self-loop in full precision
}

// K6: layer-2 aggregation directly into d_out: out[d] += zs[s].
__global__ void k_agg2(const int* __restrict__ src,
                       const int* __restrict__ dst,
                       float2* __restrict__ out) {
    int i = blockIdx.x * blockDim.x + threadIdx.x;
    int4 s = make_int4(0, 0, 0, 0), d = make_int4(0, 0, 0, 0);
    bool v = (i < N_QUADS);
    if (v) {
        s = reinterpret_cast<const int4*>(src)[i];                 // independent
        d = reinterpret_cast<const int4*>(dst)[i];
    }
    grid_dep_sync();                                               // wait: g_zs/out
    if (v) {
        float2 z0 = __half22float2(g_zs[s.x]);
        float2 z1 = __half22float2(g_zs[s.y]);
        float2 z2 = __half22float2(g_zs[s.z]);
        float2 z3 = __half22float2(g_zs[s.w]);
        red_add_v2(&out[d.x], z0.x, z0.y);
        red_add_v2(&out[d.y], z1.x, z1.y);
        red_add_v2(&out[d.z], z2.x, z2.y);
        red_add_v2(&out[d.w], z3.x, z3.y);
    }
}

// K7: destination post-scale + bias: out[n] = dinv[n]*out[n] + b2.
__global__ void k_final(const float* __restrict__ b2,
                        float2* __restrict__ out) {
    float bb0 = __ldg(&b2[0]), bb1 = __ldg(&b2[1]);                // independent
    grid_dep_sync();                                               // wait: out reds
    int n = blockIdx.x * blockDim.x + threadIdx.x;
    if (n < N_NODES) {
        float di = g_dinv[n];
        float2 o = out[n];
        out[n] = make_float2(fmaf(di, o.x, bb0), fmaf(di, o.y, bb1));
    }
}

// Host-side PDL launch wrapper (graph-capturable).
template <typename Kern, typename... Args>
static inline void pdl_launch(Kern k, int grid, int block, Args... args) {
    cudaLaunchConfig_t cfg = {};
    cfg.gridDim  = dim3(grid, 1, 1);
    cfg.blockDim = dim3(block, 1, 1);
    cfg.dynamicSmemBytes = 0;
    cfg.stream = 0;
    cudaLaunchAttribute attr[1];
    attr[0].id = cudaLaunchAttributeProgrammaticStreamSerialization;
    attr[0].val.programmaticStreamSerializationAllowed = 1;
    cfg.attrs = attr;
    cfg.numAttrs = 1;
    cudaLaunchKernelEx(&cfg, k, args...);
}

extern "C" void kernel_launch(void* const* d_in, const int* in_sizes, int n_in,
                              void* d_out, int out_size) {
    const float* x  = (const float*)d_in[0];
    const int*   ei = (const int*)d_in[1];
    const float* W1 = (const float*)d_in[2];
    const float* b1 = (const float*)d_in[3];
    const float* W2 = (const float*)d_in[4];
    const float* b2 = (const float*)d_in[5];
    float2*      out = (float2*)d_out;

    const int* src = ei;
    const int* dst = ei + N_EDGES;

    const int TB = 256;
    int nb_nodes = (N_NODES + TB - 1) / TB;
    int nb_quads = (N_QUADS + TB - 1) / TB;

    pdl_launch(k_degree,   nb_quads, TB, dst);
    pdl_launch(k_prescale, nb_nodes, TB, x);
    pdl_launch(k_agg1,     nb_quads, TB, src, dst);
    pdl_launch(k_node,     nb_nodes, TB, W1, b1, W2, out);
    pdl_launch(k_agg2,     nb_quads, TB, src, dst, out);
    pdl_launch(k_final,    nb_nodes, TB, b2, out);
}